// round 3
// baseline (speedup 1.0000x reference)
#include <cuda_runtime.h>
#include <cuda_bf16.h>
#include <cstdint>

// ---------------------------------------------------------------------------
// Fixed problem dims
// ---------------------------------------------------------------------------
static constexpr int M = 8192;
static constexpr int K = 4096;
static constexpr int N = 11008;

// Scratch: split bf16 hi/lo copies of X and Weff (W + 2*B@A folded in fp32)
__device__ __nv_bfloat16 g_Xh[(size_t)M * K];
__device__ __nv_bfloat16 g_Xl[(size_t)M * K];
__device__ __nv_bfloat16 g_Wh[(size_t)N * K];
__device__ __nv_bfloat16 g_Wl[(size_t)N * K];

// ---------------------------------------------------------------------------
// Prologue 1: split X into bf16 hi/lo
// ---------------------------------------------------------------------------
__global__ void split_x_kernel(const float4* __restrict__ X, size_t n4) {
    size_t i = (size_t)blockIdx.x * blockDim.x + threadIdx.x;
    if (i >= n4) return;
    float4 v = X[i];
    __nv_bfloat16 hx = __float2bfloat16(v.x), hy = __float2bfloat16(v.y);
    __nv_bfloat16 hz = __float2bfloat16(v.z), hw = __float2bfloat16(v.w);
    __nv_bfloat16 lx = __float2bfloat16(v.x - __bfloat162float(hx));
    __nv_bfloat16 ly = __float2bfloat16(v.y - __bfloat162float(hy));
    __nv_bfloat16 lz = __float2bfloat16(v.z - __bfloat162float(hz));
    __nv_bfloat16 lw = __float2bfloat16(v.w - __bfloat162float(hw));
    __nv_bfloat162* Xh2 = reinterpret_cast<__nv_bfloat162*>(g_Xh);
    __nv_bfloat162* Xl2 = reinterpret_cast<__nv_bfloat162*>(g_Xl);
    Xh2[2 * i]     = __halves2bfloat162(hx, hy);
    Xh2[2 * i + 1] = __halves2bfloat162(hz, hw);
    Xl2[2 * i]     = __halves2bfloat162(lx, ly);
    Xl2[2 * i + 1] = __halves2bfloat162(lz, lw);
}

// ---------------------------------------------------------------------------
// Prologue 2: Weff = W + 2.0*(B@A), split into bf16 hi/lo
// ---------------------------------------------------------------------------
static constexpr int FO = 32;
static constexpr int FI = 512;

__global__ void fold_w_kernel(const float* __restrict__ W,
                              const float* __restrict__ Bm,
                              const float* __restrict__ Am) {
    __shared__ float sA[16][FI];
    __shared__ float sB[FO][16];
    const int iBase = blockIdx.x * FI;
    const int oBase = blockIdx.y * FO;
    const int tid = threadIdx.x;

    for (int j = tid; j < 16 * FI; j += 256) {
        int r = j / FI, i = j % FI;
        sA[r][i] = Am[(size_t)r * K + iBase + i];
    }
    for (int j = tid; j < FO * 16; j += 256) {
        int o = j / 16, r = j % 16;
        sB[o][r] = Bm[(size_t)(oBase + o) * 16 + r];
    }
    __syncthreads();

    #pragma unroll 4
    for (int e = 0; e < (FO * FI) / 256; e++) {
        int idx = tid + 256 * e;
        int oo = idx / FI, ii = idx % FI;
        size_t g = (size_t)(oBase + oo) * K + iBase + ii;
        float acc = W[g];
        #pragma unroll
        for (int r = 0; r < 16; r++) acc += 2.0f * sB[oo][r] * sA[r][ii];
        __nv_bfloat16 h = __float2bfloat16(acc);
        g_Wh[g] = h;
        g_Wl[g] = __float2bfloat16(acc - __bfloat162float(h));
    }
}

// ---------------------------------------------------------------------------
// Main GEMM: mma.sync bf16x3, CTA 128x256, warp 64x64, BK=32, 3-stage cp.async
// SMEM rows: 32 bf16 = 64B data + 16B pad = 80B stride (16B-aligned, and
// i*80 mod 128 covers all 8 phases -> conflict-free ldmatrix).
// ---------------------------------------------------------------------------
static constexpr int BM = 128, BN = 256, BK = 32;
static constexpr int TM_TILES = M / BM;   // 64
static constexpr int TN_TILES = N / BN;   // 43
static constexpr int NSTAGES_K = K / BK;  // 128

static constexpr int ROWB = 80;                        // bytes per smem row
static constexpr int TILE_X = BM * ROWB;               // 10240
static constexpr int TILE_W = BN * ROWB;               // 20480
static constexpr int OFF_XH = 0;
static constexpr int OFF_XL = TILE_X;                  // 10240
static constexpr int OFF_WH = 2 * TILE_X;              // 20480
static constexpr int OFF_WL = 2 * TILE_X + TILE_W;     // 40960
static constexpr int STAGE_BYTES = 2 * TILE_X + 2 * TILE_W;  // 61440
static constexpr int NSLOTS = 3;
static constexpr int SMEM_TOTAL = NSLOTS * STAGE_BYTES;      // 184320

#define MMA_BF16(d, a, b)                                                      \
    asm volatile(                                                              \
        "mma.sync.aligned.m16n8k16.row.col.f32.bf16.bf16.f32 "                 \
        "{%0,%1,%2,%3}, {%4,%5,%6,%7}, {%8,%9}, {%0,%1,%2,%3};"                \
        : "+f"((d)[0]), "+f"((d)[1]), "+f"((d)[2]), "+f"((d)[3])               \
        : "r"((a)[0]), "r"((a)[1]), "r"((a)[2]), "r"((a)[3]),                  \
          "r"((b)[0]), "r"((b)[1]))

#define LDSM_X4(r0, r1, r2, r3, addr)                                          \
    asm volatile("ldmatrix.sync.aligned.m8n8.x4.shared.b16 {%0,%1,%2,%3}, [%4];" \
                 : "=r"(r0), "=r"(r1), "=r"(r2), "=r"(r3) : "r"(addr))

__device__ __forceinline__ void cp16(uint32_t sdst, const void* g) {
    asm volatile("cp.async.cg.shared.global [%0], [%1], 16;" :: "r"(sdst), "l"(g));
}
#define CP_COMMIT() asm volatile("cp.async.commit_group;" ::: "memory")
#define CP_WAIT(n) asm volatile("cp.async.wait_group %0;" :: "n"(n) : "memory")

__device__ __forceinline__ void issue_stage(uint32_t tb, int k0,
                                            const __nv_bfloat16* gXh,
                                            const __nv_bfloat16* gXl,
                                            const __nv_bfloat16* gWh,
                                            const __nv_bfloat16* gWl, int tid) {
    // X tiles: 128 rows x 4 16B-chunks = 512 chunks each
    #pragma unroll
    for (int j = 0; j < 2; j++) {
        int q = tid + 256 * j;
        int r = q >> 2, c = q & 3;
        cp16(tb + OFF_XH + r * ROWB + c * 16, gXh + (size_t)r * K + k0 + c * 8);
    }
    #pragma unroll
    for (int j = 0; j < 2; j++) {
        int q = tid + 256 * j;
        int r = q >> 2, c = q & 3;
        cp16(tb + OFF_XL + r * ROWB + c * 16, gXl + (size_t)r * K + k0 + c * 8);
    }
    // W tiles: 256 rows x 4 chunks = 1024 chunks each
    #pragma unroll
    for (int j = 0; j < 4; j++) {
        int q = tid + 256 * j;
        int r = q >> 2, c = q & 3;
        cp16(tb + OFF_WH + r * ROWB + c * 16, gWh + (size_t)r * K + k0 + c * 8);
    }
    #pragma unroll
    for (int j = 0; j < 4; j++) {
        int q = tid + 256 * j;
        int r = q >> 2, c = q & 3;
        cp16(tb + OFF_WL + r * ROWB + c * 16, gWl + (size_t)r * K + k0 + c * 8);
    }
    CP_COMMIT();
}

__device__ __forceinline__ void compute_stage(uint32_t tb, int wm, int wn, int lane,
                                              float acc[4][8][4]) {
    const int lrow = lane & 15;
    const int lcol = lane >> 4;  // 0/1: which 8-element k-half
    #pragma unroll
    for (int kk = 0; kk < 2; kk++) {
        const uint32_t kbyte = kk * 32 + lcol * 16;

        uint32_t ah[4][4], al[4][4];
        #pragma unroll
        for (int mt = 0; mt < 4; mt++) {
            uint32_t base = tb + (wm * 64 + mt * 16 + lrow) * ROWB + kbyte;
            LDSM_X4(ah[mt][0], ah[mt][1], ah[mt][2], ah[mt][3], base + OFF_XH);
            LDSM_X4(al[mt][0], al[mt][1], al[mt][2], al[mt][3], base + OFF_XL);
        }

        uint32_t bh[8][2], bl[8][2];
        #pragma unroll
        for (int np = 0; np < 4; np++) {
            uint32_t base = tb + (wn * 64 + np * 16 + lrow) * ROWB + kbyte;
            uint32_t t0, t1, t2, t3;
            LDSM_X4(t0, t1, t2, t3, base + OFF_WH);
            bh[2 * np][0] = t0; bh[2 * np + 1][0] = t1;
            bh[2 * np][1] = t2; bh[2 * np + 1][1] = t3;
            LDSM_X4(t0, t1, t2, t3, base + OFF_WL);
            bl[2 * np][0] = t0; bl[2 * np + 1][0] = t1;
            bl[2 * np][1] = t2; bl[2 * np + 1][1] = t3;
        }

        #pragma unroll
        for (int mt = 0; mt < 4; mt++) {
            #pragma unroll
            for (int nt = 0; nt < 8; nt++) {
                MMA_BF16(acc[mt][nt], ah[mt], bh[nt]);
                MMA_BF16(acc[mt][nt], ah[mt], bl[nt]);
                MMA_BF16(acc[mt][nt], al[mt], bh[nt]);
            }
        }
    }
}

__global__ __launch_bounds__(256, 1)
void gemm_bf16x3_kernel(const float* __restrict__ bias, float* __restrict__ C) {
    extern __shared__ __align__(1024) char smem[];
    uint32_t sb;
    asm("{ .reg .u64 t; cvta.to.shared.u64 t, %1; cvt.u32.u64 %0, t; }"
        : "=r"(sb) : "l"(smem));

    const int tid = threadIdx.x;
    const int warp = tid >> 5;
    const int lane = tid & 31;
    const int wm = warp >> 2;  // 0..1
    const int wn = warp & 3;   // 0..3

    // Supertile rasterization: groups of 8 N-tiles, M-major within each group
    int lin = blockIdx.x;
    int gid = lin >> 9;        // /512  (8 n-tiles * 64 m-tiles)
    int rem = lin & 511;
    int n0 = gid * 8;
    int width = min(8, TN_TILES - n0);
    int mT = rem / width;
    int nT = n0 + rem % width;
    const int mBase = mT * BM;
    const int nBase = nT * BN;

    const __nv_bfloat16* gXh = g_Xh + (size_t)mBase * K;
    const __nv_bfloat16* gXl = g_Xl + (size_t)mBase * K;
    const __nv_bfloat16* gWh = g_Wh + (size_t)nBase * K;
    const __nv_bfloat16* gWl = g_Wl + (size_t)nBase * K;

    float acc[4][8][4];
    #pragma unroll
    for (int a = 0; a < 4; a++)
        #pragma unroll
        for (int b = 0; b < 8; b++)
            #pragma unroll
            for (int c = 0; c < 4; c++) acc[a][b][c] = 0.0f;

    issue_stage(sb + 0 * STAGE_BYTES, 0 * BK, gXh, gXl, gWh, gWl, tid);
    issue_stage(sb + 1 * STAGE_BYTES, 1 * BK, gXh, gXl, gWh, gWl, tid);

    int slot = 0;
    for (int s = 0; s < NSTAGES_K; s++) {
        if (s + 2 < NSTAGES_K) {
            int wslot = slot - 1;
            if (wslot < 0) wslot += NSLOTS;
            issue_stage(sb + wslot * STAGE_BYTES, (s + 2) * BK, gXh, gXl, gWh, gWl, tid);
            CP_WAIT(2);
        } else if (s + 1 < NSTAGES_K) {
            CP_WAIT(1);
        } else {
            CP_WAIT(0);
        }
        __syncthreads();
        compute_stage(sb + slot * STAGE_BYTES, wm, wn, lane, acc);
        __syncthreads();
        slot++;
        if (slot == NSLOTS) slot = 0;
    }

    // Epilogue: add bias, write fp32
    const int qrow = lane >> 2;
    const int qc = (lane & 3) * 2;
    #pragma unroll
    for (int nt = 0; nt < 8; nt++) {
        int col = nBase + wn * 64 + nt * 8 + qc;
        float2 bs = *(const float2*)(bias + col);
        #pragma unroll
        for (int mt = 0; mt < 4; mt++) {
            int row = mBase + wm * 64 + mt * 16 + qrow;
            float2 v0 = make_float2(acc[mt][nt][0] + bs.x, acc[mt][nt][1] + bs.y);
            float2 v1 = make_float2(acc[mt][nt][2] + bs.x, acc[mt][nt][3] + bs.y);
            *(float2*)(C + (size_t)row * N + col) = v0;
            *(float2*)(C + (size_t)(row + 8) * N + col) = v1;
        }
    }
}

// ---------------------------------------------------------------------------
// Launch
// ---------------------------------------------------------------------------
extern "C" void kernel_launch(void* const* d_in, const int* in_sizes, int n_in,
                              void* d_out, int out_size) {
    const float* x    = (const float*)d_in[0];
    const float* W    = (const float*)d_in[1];
    const float* bias = (const float*)d_in[2];
    const float* B    = (const float*)d_in[3];
    const float* A    = (const float*)d_in[4];
    float* out = (float*)d_out;

    size_t n4 = (size_t)M * K / 4;
    split_x_kernel<<<(unsigned)((n4 + 255) / 256), 256>>>((const float4*)x, n4);
    fold_w_kernel<<<dim3(K / FI, N / FO), 256>>>(W, B, A);

    cudaFuncSetAttribute(gemm_bf16x3_kernel,
                         cudaFuncAttributeMaxDynamicSharedMemorySize, SMEM_TOTAL);
    gemm_bf16x3_kernel<<<TM_TILES * TN_TILES, 256, SMEM_TOTAL>>>(bias, out);
}

// round 4
// speedup vs baseline: 1.7624x; 1.7624x over previous
#include <cuda_runtime.h>
#include <cuda_fp16.h>
#include <cstdint>

// ---------------------------------------------------------------------------
// Fixed problem dims
// ---------------------------------------------------------------------------
static constexpr int M = 8192;
static constexpr int K = 4096;
static constexpr int N = 11008;

// Scratch: xh = fp16(x); Weff = W + 2*B@A split into fp16 hi/lo
__device__ __half g_Xh[(size_t)M * K];
__device__ __half g_Wh[(size_t)N * K];
__device__ __half g_Wl[(size_t)N * K];

// ---------------------------------------------------------------------------
// Prologue 1: convert X to fp16
// ---------------------------------------------------------------------------
__global__ void conv_x_kernel(const float4* __restrict__ X, size_t n4) {
    size_t i = (size_t)blockIdx.x * blockDim.x + threadIdx.x;
    if (i >= n4) return;
    float4 v = X[i];
    __half2* Xh2 = reinterpret_cast<__half2*>(g_Xh);
    Xh2[2 * i]     = __floats2half2_rn(v.x, v.y);
    Xh2[2 * i + 1] = __floats2half2_rn(v.z, v.w);
}

// ---------------------------------------------------------------------------
// Prologue 2: Weff = W + 2.0*(B@A), split into fp16 hi/lo
// ---------------------------------------------------------------------------
static constexpr int FO = 32;
static constexpr int FI = 512;

__global__ void fold_w_kernel(const float* __restrict__ W,
                              const float* __restrict__ Bm,
                              const float* __restrict__ Am) {
    __shared__ float sA[16][FI];
    __shared__ float sB[FO][16];
    const int iBase = blockIdx.x * FI;
    const int oBase = blockIdx.y * FO;
    const int tid = threadIdx.x;

    for (int j = tid; j < 16 * FI; j += 256) {
        int r = j / FI, i = j % FI;
        sA[r][i] = Am[(size_t)r * K + iBase + i];
    }
    for (int j = tid; j < FO * 16; j += 256) {
        int o = j / 16, r = j % 16;
        sB[o][r] = Bm[(size_t)(oBase + o) * 16 + r];
    }
    __syncthreads();

    #pragma unroll 4
    for (int e = 0; e < (FO * FI) / 256; e++) {
        int idx = tid + 256 * e;
        int oo = idx / FI, ii = idx % FI;
        size_t g = (size_t)(oBase + oo) * K + iBase + ii;
        float acc = W[g];
        #pragma unroll
        for (int r = 0; r < 16; r++) acc += 2.0f * sB[oo][r] * sA[r][ii];
        __half h = __float2half_rn(acc);
        g_Wh[g] = h;
        g_Wl[g] = __float2half_rn(acc - __half2float(h));
    }
}

// ---------------------------------------------------------------------------
// Main GEMM: C = Xh@Wh^T + Xh@Wl^T + bias    (fp16x2 ~ fp16-input fp32 result)
// CTA tile 128x128xK, BK=32, 8 warps (2x4), warp tile 64x32, mma.m16n8k16.
// ---------------------------------------------------------------------------
static constexpr int BM = 128, BN = 128, BK = 32;
static constexpr int LDT = BK + 8;                 // padded fp16 row (conflict-free)
static constexpr int TILE_ELEMS = BM * LDT;        // 5120 halves per operand tile
static constexpr int STAGE_ELEMS = 3 * TILE_ELEMS; // xh, wh, wl
static constexpr int SMEM_BYTES = 2 * STAGE_ELEMS * (int)sizeof(__half); // 61440

#define MMA_FP16(d, a, b)                                                      \
    asm volatile(                                                              \
        "mma.sync.aligned.m16n8k16.row.col.f32.f16.f16.f32 "                   \
        "{%0,%1,%2,%3}, {%4,%5,%6,%7}, {%8,%9}, {%0,%1,%2,%3};"                \
        : "+f"((d)[0]), "+f"((d)[1]), "+f"((d)[2]), "+f"((d)[3])               \
        : "r"((a)[0]), "r"((a)[1]), "r"((a)[2]), "r"((a)[3]),                  \
          "r"((b)[0]), "r"((b)[1]))

__device__ __forceinline__ void cp16(uint32_t sdst, const void* g) {
    asm volatile("cp.async.cg.shared.global [%0], [%1], 16;" :: "r"(sdst), "l"(g));
}
#define CP_COMMIT() asm volatile("cp.async.commit_group;" ::: "memory")
#define CP_WAIT(n) asm volatile("cp.async.wait_group %0;" :: "n"(n) : "memory")

__device__ __forceinline__ void issue_stage(__half* st, int k0,
                                            int mBase, int nBase, int tid) {
    const __half* srcs[3] = {
        g_Xh + (size_t)mBase * K, g_Wh + (size_t)nBase * K, g_Wl + (size_t)nBase * K};
    #pragma unroll
    for (int j = 0; j < 6; j++) {
        int c = tid + 256 * j;       // 0..1535 16B chunks
        int t3 = c >> 9;             // which operand tile (0..2)
        int idx = c & 511;
        int row = idx >> 2;
        int col16 = idx & 3;         // 8-elem (16B) column group
        const __half* g = srcs[t3] + (size_t)row * K + k0 + col16 * 8;
        __half* sdst = st + t3 * TILE_ELEMS + row * LDT + col16 * 8;
        uint32_t sa = (uint32_t)__cvta_generic_to_shared(sdst);
        cp16(sa, g);
    }
    CP_COMMIT();
}

__device__ __forceinline__ void compute_stage(const __half* st, int wm, int wn,
                                              int lane, float acc[4][4][4]) {
    const __half* Xhs = st;
    const __half* Whs = st + TILE_ELEMS;
    const __half* Wls = st + 2 * TILE_ELEMS;
    const int qrow = lane >> 2;
    const int qk = (lane & 3) * 2;
    #pragma unroll
    for (int kk = 0; kk < 2; kk++) {
        const int kb = kk * 16 + qk;
        uint32_t bh[4][2], bl[4][2];
        #pragma unroll
        for (int nt = 0; nt < 4; nt++) {
            int n0 = wn * 32 + nt * 8 + qrow;
            bh[nt][0] = *(const uint32_t*)(Whs + n0 * LDT + kb);
            bh[nt][1] = *(const uint32_t*)(Whs + n0 * LDT + kb + 8);
            bl[nt][0] = *(const uint32_t*)(Wls + n0 * LDT + kb);
            bl[nt][1] = *(const uint32_t*)(Wls + n0 * LDT + kb + 8);
        }
        #pragma unroll
        for (int mt = 0; mt < 4; mt++) {
            int m0 = wm * 64 + mt * 16 + qrow;
            uint32_t ah[4];
            ah[0] = *(const uint32_t*)(Xhs + m0 * LDT + kb);
            ah[1] = *(const uint32_t*)(Xhs + (m0 + 8) * LDT + kb);
            ah[2] = *(const uint32_t*)(Xhs + m0 * LDT + kb + 8);
            ah[3] = *(const uint32_t*)(Xhs + (m0 + 8) * LDT + kb + 8);
            #pragma unroll
            for (int nt = 0; nt < 4; nt++) {
                MMA_FP16(acc[mt][nt], ah, bh[nt]);
                MMA_FP16(acc[mt][nt], ah, bl[nt]);
            }
        }
    }
}

__global__ __launch_bounds__(256, 1)
void gemm_fp16x2_kernel(const float* __restrict__ bias, float* __restrict__ C) {
    extern __shared__ __half smem[];
    const int tid = threadIdx.x;
    const int warp = tid >> 5;
    const int lane = tid & 31;
    const int wm = warp >> 2;  // 0..1
    const int wn = warp & 3;   // 0..3
    const int mBase = blockIdx.y * BM;
    const int nBase = blockIdx.x * BN;

    float acc[4][4][4];
    #pragma unroll
    for (int a = 0; a < 4; a++)
        #pragma unroll
        for (int b = 0; b < 4; b++)
            #pragma unroll
            for (int c = 0; c < 4; c++) acc[a][b][c] = 0.0f;

    const int nsteps = K / BK;
    issue_stage(smem, 0, mBase, nBase, tid);

    for (int s = 0; s < nsteps; s++) {
        if (s + 1 < nsteps) {
            issue_stage(smem + ((s + 1) & 1) * STAGE_ELEMS, (s + 1) * BK,
                        mBase, nBase, tid);
            CP_WAIT(1);
        } else {
            CP_WAIT(0);
        }
        __syncthreads();
        compute_stage(smem + (s & 1) * STAGE_ELEMS, wm, wn, lane, acc);
        __syncthreads();
    }

    // Epilogue: add bias, write fp32
    const int qrow = lane >> 2;
    const int qc = (lane & 3) * 2;
    #pragma unroll
    for (int nt = 0; nt < 4; nt++) {
        int col = nBase + wn * 32 + nt * 8 + qc;
        float2 bs = *(const float2*)(bias + col);
        #pragma unroll
        for (int mt = 0; mt < 4; mt++) {
            int row = mBase + wm * 64 + mt * 16 + qrow;
            float2 v0 = make_float2(acc[mt][nt][0] + bs.x, acc[mt][nt][1] + bs.y);
            float2 v1 = make_float2(acc[mt][nt][2] + bs.x, acc[mt][nt][3] + bs.y);
            *(float2*)(C + (size_t)row * N + col) = v0;
            *(float2*)(C + (size_t)(row + 8) * N + col) = v1;
        }
    }
}

// ---------------------------------------------------------------------------
// Launch
// ---------------------------------------------------------------------------
extern "C" void kernel_launch(void* const* d_in, const int* in_sizes, int n_in,
                              void* d_out, int out_size) {
    const float* x    = (const float*)d_in[0];
    const float* W    = (const float*)d_in[1];
    const float* bias = (const float*)d_in[2];
    const float* B    = (const float*)d_in[3];
    const float* A    = (const float*)d_in[4];
    float* out = (float*)d_out;

    size_t n4 = (size_t)M * K / 4;
    conv_x_kernel<<<(unsigned)((n4 + 255) / 256), 256>>>((const float4*)x, n4);
    fold_w_kernel<<<dim3(K / FI, N / FO), 256>>>(W, B, A);

    cudaFuncSetAttribute(gemm_fp16x2_kernel,
                         cudaFuncAttributeMaxDynamicSharedMemorySize, SMEM_BYTES);
    dim3 grid(N / BN, M / BM);
    gemm_fp16x2_kernel<<<grid, 256, SMEM_BYTES>>>(bias, out);
}

// round 5
// speedup vs baseline: 2.7651x; 1.5690x over previous
#include <cuda_runtime.h>
#include <cuda_fp16.h>
#include <cstdint>

// ---------------------------------------------------------------------------
// Fixed problem dims
// ---------------------------------------------------------------------------
static constexpr int M = 8192;
static constexpr int K = 4096;
static constexpr int N = 11008;

// Scratch: xh = fp16(x); wh = fp16(W + 2*B@A)
__device__ __half g_Xh[(size_t)M * K];
__device__ __half g_Wh[(size_t)N * K];

// ---------------------------------------------------------------------------
// Prologue 1: convert X to fp16
// ---------------------------------------------------------------------------
__global__ void conv_x_kernel(const float4* __restrict__ X, size_t n4) {
    size_t i = (size_t)blockIdx.x * blockDim.x + threadIdx.x;
    if (i >= n4) return;
    float4 v = X[i];
    __half2* Xh2 = reinterpret_cast<__half2*>(g_Xh);
    Xh2[2 * i]     = __floats2half2_rn(v.x, v.y);
    Xh2[2 * i + 1] = __floats2half2_rn(v.z, v.w);
}

// ---------------------------------------------------------------------------
// Prologue 2: Weff = W + 2.0*(B@A) -> fp16
// ---------------------------------------------------------------------------
static constexpr int FO = 32;
static constexpr int FI = 512;

__global__ void fold_w_kernel(const float* __restrict__ W,
                              const float* __restrict__ Bm,
                              const float* __restrict__ Am) {
    __shared__ float sA[16][FI];
    __shared__ float sB[FO][16];
    const int iBase = blockIdx.x * FI;
    const int oBase = blockIdx.y * FO;
    const int tid = threadIdx.x;

    for (int j = tid; j < 16 * FI; j += 256) {
        int r = j / FI, i = j % FI;
        sA[r][i] = Am[(size_t)r * K + iBase + i];
    }
    for (int j = tid; j < FO * 16; j += 256) {
        int o = j / 16, r = j % 16;
        sB[o][r] = Bm[(size_t)(oBase + o) * 16 + r];
    }
    __syncthreads();

    #pragma unroll 4
    for (int e = 0; e < (FO * FI) / 256; e++) {
        int idx = tid + 256 * e;
        int oo = idx / FI, ii = idx % FI;
        size_t g = (size_t)(oBase + oo) * K + iBase + ii;
        float acc = W[g];
        #pragma unroll
        for (int r = 0; r < 16; r++) acc += 2.0f * sB[oo][r] * sA[r][ii];
        g_Wh[g] = __float2half_rn(acc);
    }
}

// ---------------------------------------------------------------------------
// Main GEMM: C = Xh@Wh^T + bias   (single-pass fp16, fp32 accumulate)
// CTA tile 128x128xK, BK=32, 8 warps (2x4), warp tile 64x32, mma.m16n8k16.
// ---------------------------------------------------------------------------
static constexpr int BM = 128, BN = 128, BK = 32;
static constexpr int LDT = BK + 8;                 // padded fp16 row (conflict-free)
static constexpr int TILE_ELEMS = BM * LDT;        // 5120 halves per operand tile
static constexpr int STAGE_ELEMS = 2 * TILE_ELEMS; // xh, wh
static constexpr int SMEM_BYTES = 2 * STAGE_ELEMS * (int)sizeof(__half); // 40960

#define MMA_FP16(d, a, b)                                                      \
    asm volatile(                                                              \
        "mma.sync.aligned.m16n8k16.row.col.f32.f16.f16.f32 "                   \
        "{%0,%1,%2,%3}, {%4,%5,%6,%7}, {%8,%9}, {%0,%1,%2,%3};"                \
        : "+f"((d)[0]), "+f"((d)[1]), "+f"((d)[2]), "+f"((d)[3])               \
        : "r"((a)[0]), "r"((a)[1]), "r"((a)[2]), "r"((a)[3]),                  \
          "r"((b)[0]), "r"((b)[1]))

__device__ __forceinline__ void cp16(uint32_t sdst, const void* g) {
    asm volatile("cp.async.cg.shared.global [%0], [%1], 16;" :: "r"(sdst), "l"(g));
}
#define CP_COMMIT() asm volatile("cp.async.commit_group;" ::: "memory")
#define CP_WAIT(n) asm volatile("cp.async.wait_group %0;" :: "n"(n) : "memory")

__device__ __forceinline__ void issue_stage(__half* st, int k0,
                                            int mBase, int nBase, int tid) {
    const __half* srcs[2] = {g_Xh + (size_t)mBase * K, g_Wh + (size_t)nBase * K};
    #pragma unroll
    for (int j = 0; j < 4; j++) {
        int c = tid + 256 * j;       // 0..1023 16B chunks
        int t2 = c >> 9;             // which operand tile (0..1)
        int idx = c & 511;
        int row = idx >> 2;
        int col16 = idx & 3;         // 8-elem (16B) column group
        const __half* g = srcs[t2] + (size_t)row * K + k0 + col16 * 8;
        __half* sdst = st + t2 * TILE_ELEMS + row * LDT + col16 * 8;
        cp16((uint32_t)__cvta_generic_to_shared(sdst), g);
    }
    CP_COMMIT();
}

__device__ __forceinline__ void compute_stage(const __half* st, int wm, int wn,
                                              int lane, float acc[4][4][4]) {
    const __half* Xhs = st;
    const __half* Whs = st + TILE_ELEMS;
    const int qrow = lane >> 2;
    const int qk = (lane & 3) * 2;
    #pragma unroll
    for (int kk = 0; kk < 2; kk++) {
        const int kb = kk * 16 + qk;
        uint32_t bh[4][2];
        #pragma unroll
        for (int nt = 0; nt < 4; nt++) {
            int n0 = wn * 32 + nt * 8 + qrow;
            bh[nt][0] = *(const uint32_t*)(Whs + n0 * LDT + kb);
            bh[nt][1] = *(const uint32_t*)(Whs + n0 * LDT + kb + 8);
        }
        #pragma unroll
        for (int mt = 0; mt < 4; mt++) {
            int m0 = wm * 64 + mt * 16 + qrow;
            uint32_t ah[4];
            ah[0] = *(const uint32_t*)(Xhs + m0 * LDT + kb);
            ah[1] = *(const uint32_t*)(Xhs + (m0 + 8) * LDT + kb);
            ah[2] = *(const uint32_t*)(Xhs + m0 * LDT + kb + 8);
            ah[3] = *(const uint32_t*)(Xhs + (m0 + 8) * LDT + kb + 8);
            #pragma unroll
            for (int nt = 0; nt < 4; nt++) {
                MMA_FP16(acc[mt][nt], ah, bh[nt]);
            }
        }
    }
}

__global__ __launch_bounds__(256, 1)
void gemm_fp16_kernel(const float* __restrict__ bias, float* __restrict__ C) {
    extern __shared__ __half smem[];
    const int tid = threadIdx.x;
    const int warp = tid >> 5;
    const int lane = tid & 31;
    const int wm = warp >> 2;  // 0..1
    const int wn = warp & 3;   // 0..3
    const int mBase = blockIdx.y * BM;
    const int nBase = blockIdx.x * BN;

    float acc[4][4][4];
    #pragma unroll
    for (int a = 0; a < 4; a++)
        #pragma unroll
        for (int b = 0; b < 4; b++)
            #pragma unroll
            for (int c = 0; c < 4; c++) acc[a][b][c] = 0.0f;

    const int nsteps = K / BK;
    issue_stage(smem, 0, mBase, nBase, tid);

    for (int s = 0; s < nsteps; s++) {
        if (s + 1 < nsteps) {
            issue_stage(smem + ((s + 1) & 1) * STAGE_ELEMS, (s + 1) * BK,
                        mBase, nBase, tid);
            CP_WAIT(1);
        } else {
            CP_WAIT(0);
        }
        __syncthreads();
        compute_stage(smem + (s & 1) * STAGE_ELEMS, wm, wn, lane, acc);
        __syncthreads();
    }

    // Epilogue: add bias, write fp32
    const int qrow = lane >> 2;
    const int qc = (lane & 3) * 2;
    #pragma unroll
    for (int nt = 0; nt < 4; nt++) {
        int col = nBase + wn * 32 + nt * 8 + qc;
        float2 bs = *(const float2*)(bias + col);
        #pragma unroll
        for (int mt = 0; mt < 4; mt++) {
            int row = mBase + wm * 64 + mt * 16 + qrow;
            float2 v0 = make_float2(acc[mt][nt][0] + bs.x, acc[mt][nt][1] + bs.y);
            float2 v1 = make_float2(acc[mt][nt][2] + bs.x, acc[mt][nt][3] + bs.y);
            *(float2*)(C + (size_t)row * N + col) = v0;
            *(float2*)(C + (size_t)(row + 8) * N + col) = v1;
        }
    }
}

// ---------------------------------------------------------------------------
// Launch
// ---------------------------------------------------------------------------
extern "C" void kernel_launch(void* const* d_in, const int* in_sizes, int n_in,
                              void* d_out, int out_size) {
    const float* x    = (const float*)d_in[0];
    const float* W    = (const float*)d_in[1];
    const float* bias = (const float*)d_in[2];
    const float* B    = (const float*)d_in[3];
    const float* A    = (const float*)d_in[4];
    float* out = (float*)d_out;

    size_t n4 = (size_t)M * K / 4;
    conv_x_kernel<<<(unsigned)((n4 + 255) / 256), 256>>>((const float4*)x, n4);
    fold_w_kernel<<<dim3(K / FI, N / FO), 256>>>(W, B, A);

    cudaFuncSetAttribute(gemm_fp16_kernel,
                         cudaFuncAttributeMaxDynamicSharedMemorySize, SMEM_BYTES);
    dim3 grid(N / BN, M / BM);
    gemm_fp16_kernel<<<grid, 256, SMEM_BYTES>>>(bias, out);
}

// round 6
// speedup vs baseline: 2.9710x; 1.0744x over previous
#include <cuda_runtime.h>
#include <cuda_fp16.h>
#include <cstdint>

// ---------------------------------------------------------------------------
// Fixed problem dims
// ---------------------------------------------------------------------------
static constexpr int M = 8192;
static constexpr int K = 4096;
static constexpr int N = 11008;

// Scratch: xh = fp16(x); wh = fp16(W + 2*B@A)
__device__ __half g_Xh[(size_t)M * K];
__device__ __half g_Wh[(size_t)N * K];

// ---------------------------------------------------------------------------
// Prologue 1: convert X to fp16
// ---------------------------------------------------------------------------
__global__ void conv_x_kernel(const float4* __restrict__ X, size_t n4) {
    size_t i = (size_t)blockIdx.x * blockDim.x + threadIdx.x;
    if (i >= n4) return;
    float4 v = X[i];
    __half2* Xh2 = reinterpret_cast<__half2*>(g_Xh);
    Xh2[2 * i]     = __floats2half2_rn(v.x, v.y);
    Xh2[2 * i + 1] = __floats2half2_rn(v.z, v.w);
}

// ---------------------------------------------------------------------------
// Prologue 2: Weff = W + 2.0*(B@A) -> fp16
// ---------------------------------------------------------------------------
static constexpr int FO = 32;
static constexpr int FI = 512;

__global__ void fold_w_kernel(const float* __restrict__ W,
                              const float* __restrict__ Bm,
                              const float* __restrict__ Am) {
    __shared__ float sA[16][FI];
    __shared__ float sB[FO][16];
    const int iBase = blockIdx.x * FI;
    const int oBase = blockIdx.y * FO;
    const int tid = threadIdx.x;

    for (int j = tid; j < 16 * FI; j += 256) {
        int r = j / FI, i = j % FI;
        sA[r][i] = Am[(size_t)r * K + iBase + i];
    }
    for (int j = tid; j < FO * 16; j += 256) {
        int o = j / 16, r = j % 16;
        sB[o][r] = Bm[(size_t)(oBase + o) * 16 + r];
    }
    __syncthreads();

    #pragma unroll 4
    for (int e = 0; e < (FO * FI) / 256; e++) {
        int idx = tid + 256 * e;
        int oo = idx / FI, ii = idx % FI;
        size_t g = (size_t)(oBase + oo) * K + iBase + ii;
        float acc = W[g];
        #pragma unroll
        for (int r = 0; r < 16; r++) acc += 2.0f * sB[oo][r] * sA[r][ii];
        g_Wh[g] = __float2half_rn(acc);
    }
}

// ---------------------------------------------------------------------------
// Main GEMM: C = Xh@Wh^T + bias  (single-pass fp16, fp32 accumulate)
// CTA 128x128, warp 64x32 (8 warps 2x4), BK=64, ldmatrix.x4, 3-stage cp.async.
// SMEM rows: 64 halves = 128B data + 16B pad = 144B stride; 144*i mod 128
// covers all 8 16B-phases -> conflict-free ldmatrix + cp.async stores.
// ---------------------------------------------------------------------------
static constexpr int BM = 128, BN = 128, BK = 64;
static constexpr int TM_TILES = M / BM;   // 64
static constexpr int TN_TILES = N / BN;   // 86
static constexpr int NSTAGES_K = K / BK;  // 64

static constexpr int ROWB = 144;                      // bytes per smem row
static constexpr int TILE_X = BM * ROWB;              // 18432
static constexpr int TILE_W = BN * ROWB;              // 18432
static constexpr int OFF_X = 0;
static constexpr int OFF_W = TILE_X;
static constexpr int STAGE_BYTES = TILE_X + TILE_W;   // 36864
static constexpr int NSLOTS = 3;
static constexpr int SMEM_TOTAL = NSLOTS * STAGE_BYTES;  // 110592 (108KB)

#define MMA_FP16(d, a, b)                                                      \
    asm volatile(                                                              \
        "mma.sync.aligned.m16n8k16.row.col.f32.f16.f16.f32 "                   \
        "{%0,%1,%2,%3}, {%4,%5,%6,%7}, {%8,%9}, {%0,%1,%2,%3};"                \
        : "+f"((d)[0]), "+f"((d)[1]), "+f"((d)[2]), "+f"((d)[3])               \
        : "r"((a)[0]), "r"((a)[1]), "r"((a)[2]), "r"((a)[3]),                  \
          "r"((b)[0]), "r"((b)[1]))

#define LDSM_X4(r0, r1, r2, r3, addr)                                          \
    asm volatile("ldmatrix.sync.aligned.m8n8.x4.shared.b16 {%0,%1,%2,%3}, [%4];" \
                 : "=r"(r0), "=r"(r1), "=r"(r2), "=r"(r3) : "r"(addr))

__device__ __forceinline__ void cp16(uint32_t sdst, const void* g) {
    asm volatile("cp.async.cg.shared.global [%0], [%1], 16;" :: "r"(sdst), "l"(g));
}
#define CP_COMMIT() asm volatile("cp.async.commit_group;" ::: "memory")
#define CP_WAIT(n) asm volatile("cp.async.wait_group %0;" :: "n"(n) : "memory")

__device__ __forceinline__ void issue_stage(uint32_t tb, int k0,
                                            const __half* gX, const __half* gW,
                                            int tid) {
    // X: 128 rows x 8 16B-chunks = 1024 chunks; W same; 2048 total, 8/thread
    #pragma unroll
    for (int j = 0; j < 4; j++) {
        int q = tid + 256 * j;
        int r = q >> 3, c = q & 7;
        cp16(tb + OFF_X + r * ROWB + c * 16, gX + (size_t)r * K + k0 + c * 8);
    }
    #pragma unroll
    for (int j = 0; j < 4; j++) {
        int q = tid + 256 * j;
        int r = q >> 3, c = q & 7;
        cp16(tb + OFF_W + r * ROWB + c * 16, gW + (size_t)r * K + k0 + c * 8);
    }
    CP_COMMIT();
}

__device__ __forceinline__ void compute_stage(uint32_t tb, int wm, int wn, int lane,
                                              float acc[4][4][4]) {
    const int lrow = lane & 15;
    const int lcol = lane >> 4;  // 0/1: which 8-elem k-half within 16
    #pragma unroll
    for (int kk = 0; kk < 4; kk++) {
        const uint32_t kbyte = kk * 32 + lcol * 16;

        // B fragments: warp covers 32 N-rows = 2 LDSM.x4 groups of 16
        uint32_t bh[4][2];
        #pragma unroll
        for (int np = 0; np < 2; np++) {
            uint32_t base = tb + OFF_W + (wn * 32 + np * 16 + lrow) * ROWB + kbyte;
            uint32_t t0, t1, t2, t3;
            LDSM_X4(t0, t1, t2, t3, base);
            bh[2 * np][0] = t0; bh[2 * np + 1][0] = t1;
            bh[2 * np][1] = t2; bh[2 * np + 1][1] = t3;
        }

        // A fragments + MMAs
        #pragma unroll
        for (int mt = 0; mt < 4; mt++) {
            uint32_t base = tb + OFF_X + (wm * 64 + mt * 16 + lrow) * ROWB + kbyte;
            uint32_t ah[4];
            LDSM_X4(ah[0], ah[1], ah[2], ah[3], base);
            #pragma unroll
            for (int nt = 0; nt < 4; nt++) {
                MMA_FP16(acc[mt][nt], ah, bh[nt]);
            }
        }
    }
}

__global__ __launch_bounds__(256, 2)
void gemm_fp16_kernel(const float* __restrict__ bias, float* __restrict__ C) {
    extern __shared__ __align__(1024) char smem[];
    uint32_t sb;
    asm("{ .reg .u64 t; cvta.to.shared.u64 t, %1; cvt.u32.u64 %0, t; }"
        : "=r"(sb) : "l"(smem));

    const int tid = threadIdx.x;
    const int warp = tid >> 5;
    const int lane = tid & 31;
    const int wm = warp >> 2;  // 0..1
    const int wn = warp & 3;   // 0..3

    // Supertile raster: groups of 16 N-tiles, M-major within each group
    int lin = blockIdx.x;
    int gid = lin >> 10;            // / (16*64)
    int rem = lin & 1023;
    int n0 = gid * 16;
    int width = min(16, TN_TILES - n0);
    int mT = rem / width;
    int nT = n0 + rem % width;
    const int mBase = mT * BM;
    const int nBase = nT * BN;

    const __half* gX = g_Xh + (size_t)mBase * K;
    const __half* gW = g_Wh + (size_t)nBase * K;

    float acc[4][4][4];
    #pragma unroll
    for (int a = 0; a < 4; a++)
        #pragma unroll
        for (int b = 0; b < 4; b++)
            #pragma unroll
            for (int c = 0; c < 4; c++) acc[a][b][c] = 0.0f;

    issue_stage(sb + 0 * STAGE_BYTES, 0 * BK, gX, gW, tid);
    issue_stage(sb + 1 * STAGE_BYTES, 1 * BK, gX, gW, tid);

    int slot = 0;
    for (int s = 0; s < NSTAGES_K; s++) {
        if (s + 2 < NSTAGES_K) {
            int wslot = slot - 1;
            if (wslot < 0) wslot += NSLOTS;
            issue_stage(sb + wslot * STAGE_BYTES, (s + 2) * BK, gX, gW, tid);
            CP_WAIT(2);
        } else if (s + 1 < NSTAGES_K) {
            CP_WAIT(1);
        } else {
            CP_WAIT(0);
        }
        __syncthreads();
        compute_stage(sb + slot * STAGE_BYTES, wm, wn, lane, acc);
        __syncthreads();
        slot++;
        if (slot == NSLOTS) slot = 0;
    }

    // Epilogue: add bias, write fp32
    const int qrow = lane >> 2;
    const int qc = (lane & 3) * 2;
    #pragma unroll
    for (int nt = 0; nt < 4; nt++) {
        int col = nBase + wn * 32 + nt * 8 + qc;
        float2 bs = *(const float2*)(bias + col);
        #pragma unroll
        for (int mt = 0; mt < 4; mt++) {
            int row = mBase + wm * 64 + mt * 16 + qrow;
            float2 v0 = make_float2(acc[mt][nt][0] + bs.x, acc[mt][nt][1] + bs.y);
            float2 v1 = make_float2(acc[mt][nt][2] + bs.x, acc[mt][nt][3] + bs.y);
            *(float2*)(C + (size_t)row * N + col) = v0;
            *(float2*)(C + (size_t)(row + 8) * N + col) = v1;
        }
    }
}

// ---------------------------------------------------------------------------
// Launch
// ---------------------------------------------------------------------------
extern "C" void kernel_launch(void* const* d_in, const int* in_sizes, int n_in,
                              void* d_out, int out_size) {
    const float* x    = (const float*)d_in[0];
    const float* W    = (const float*)d_in[1];
    const float* bias = (const float*)d_in[2];
    const float* B    = (const float*)d_in[3];
    const float* A    = (const float*)d_in[4];
    float* out = (float*)d_out;

    size_t n4 = (size_t)M * K / 4;
    conv_x_kernel<<<(unsigned)((n4 + 255) / 256), 256>>>((const float4*)x, n4);
    fold_w_kernel<<<dim3(K / FI, N / FO), 256>>>(W, B, A);

    cudaFuncSetAttribute(gemm_fp16_kernel,
                         cudaFuncAttributeMaxDynamicSharedMemorySize, SMEM_TOTAL);
    gemm_fp16_kernel<<<TM_TILES * TN_TILES, 256, SMEM_TOTAL>>>(bias, out);
}